// round 13
// baseline (speedup 1.0000x reference)
#include <cuda_runtime.h>
#include <cuda_bf16.h>
#include <cstdint>

// Problem constants
#define E_DIM   1024
#define HEADS   16
#define HDIM    64
#define BATCH   4
#define SEQ     2048
#define ROWS    (BATCH*SEQ)        // 8192
#define NQUBITS 6
#define EW      (E_DIM/2)          // 512 packed words per E row
#define DW      (HDIM/2)           // 32 packed words per head row

// ---------------- helpers ----------------
__device__ __forceinline__ void mma_bf16(
    float* d, const uint32_t* a, const uint32_t* b)
{
    asm volatile(
        "mma.sync.aligned.m16n8k16.row.col.f32.bf16.bf16.f32 "
        "{%0,%1,%2,%3}, {%4,%5,%6,%7}, {%8,%9}, {%0,%1,%2,%3};"
        : "+f"(d[0]), "+f"(d[1]), "+f"(d[2]), "+f"(d[3])
        : "r"(a[0]), "r"(a[1]), "r"(a[2]), "r"(a[3]), "r"(b[0]), "r"(b[1]));
}
__device__ __forceinline__ void split2(float x, float y,
                                       uint32_t& hw, uint32_t& lw)
{
    __nv_bfloat16 hx = __float2bfloat16(x);
    __nv_bfloat16 hy = __float2bfloat16(y);
    __nv_bfloat162 h2; h2.x = hx; h2.y = hy;
    __nv_bfloat162 l2;
    l2.x = __float2bfloat16(x - __bfloat162float(hx));
    l2.y = __float2bfloat16(y - __bfloat162float(hy));
    hw = *reinterpret_cast<uint32_t*>(&h2);
    lw = *reinterpret_cast<uint32_t*>(&l2);
}
__device__ __forceinline__ uint32_t sptr(const void* p) {
    return (uint32_t)__cvta_generic_to_shared(p);
}
__device__ __forceinline__ void cp16(uint32_t dst, const void* src) {
    asm volatile("cp.async.cg.shared.global [%0], [%1], 16;" :: "r"(dst), "l"(src));
}
#define CP_COMMIT() asm volatile("cp.async.commit_group;" ::: "memory")
#define CP_WAIT0()  asm volatile("cp.async.wait_group 0;" ::: "memory")
__device__ __forceinline__ void ldmx4(uint32_t* r, uint32_t addr) {
    asm volatile("ldmatrix.sync.aligned.m8n8.x4.shared.b16 {%0,%1,%2,%3}, [%4];"
        : "=r"(r[0]), "=r"(r[1]), "=r"(r[2]), "=r"(r[3]) : "r"(addr));
}

// ---------------- device scratch ----------------
__device__ float    g_Mq[HDIM*HDIM];
__device__ float    g_Mk[HDIM*HDIM];
__device__ float    g_bq[E_DIM];
__device__ float    g_bk[E_DIM];
__device__ uint32_t g_Wqh[E_DIM*EW], g_Wql[E_DIM*EW];
__device__ uint32_t g_Wkh[E_DIM*EW], g_Wkl[E_DIM*EW];
__device__ uint32_t g_Wvh[E_DIM*EW], g_Wvl[E_DIM*EW];
__device__ uint32_t g_Woh[E_DIM*EW], g_Wol[E_DIM*EW];
__device__ uint32_t g_Xqh[(size_t)ROWS*EW], g_Xql[(size_t)ROWS*EW];
__device__ uint32_t g_Xkh[(size_t)ROWS*EW], g_Xkl[(size_t)ROWS*EW];
__device__ uint32_t g_Xvh[(size_t)ROWS*EW], g_Xvl[(size_t)ROWS*EW];
__device__ uint32_t g_Qh[(size_t)ROWS*EW],  g_Ql[(size_t)ROWS*EW];
__device__ uint32_t g_Kh[(size_t)ROWS*EW],  g_Kl[(size_t)ROWS*EW];
__device__ float    g_Vf[(size_t)ROWS*E_DIM];
__device__ uint32_t g_Vth[(size_t)64*HDIM*(SEQ/2)], g_Vtl[(size_t)64*HDIM*(SEQ/2)];
__device__ uint32_t g_Oh[(size_t)ROWS*EW],  g_Ol[(size_t)ROWS*EW];

// ============================================================================
// Kernel 1: build effective quantum operator (tiny, exact fp32).
// ============================================================================
__global__ void build_eff_kernel(
    const float* __restrict__ theta, const float* __restrict__ phi,
    const float* __restrict__ preW,  const float* __restrict__ preb,
    const float* __restrict__ postW, const float* __restrict__ postb,
    const float* __restrict__ b_in,
    float* __restrict__ Meff, float* __restrict__ beff)
{
    __shared__ float R[HDIM][HDIM];
    __shared__ float T[HDIM][HDIM];
    __shared__ float rb[HDIM];
    __shared__ float ctb[NQUBITS], stb[NQUBITS], cpb[NQUBITS];

    const int t = threadIdx.x;
    if (t < NQUBITS) {
        ctb[t] = cosf(theta[t]);
        stb[t] = sinf(theta[t]);
        cpb[t] = cosf(phi[t]);
    }
    __syncthreads();

    float v[HDIM];
    for (int i = 0; i < HDIM; i++) v[i] = (i == t) ? 1.f : 0.f;
    for (int q = 0; q < NQUBITS; q++) {
        const int mask = 1 << q;
        const float c = ctb[q], s = stb[q], p = cpb[q];
        for (int i0 = 0; i0 < HDIM; i0++) {
            if (i0 & mask) continue;
            const int i1 = i0 | mask;
            float x0 = v[i0], x1 = v[i1];
            v[i0] = c * x0 - s * x1;
            v[i1] = (s * x0 + c * x1) * p;
        }
    }
    for (int i = 0; i < HDIM; i++) R[i][t] = v[i];
    __syncthreads();

    for (int i = 0; i < HDIM; i++) {
        float acc = 0.f;
        for (int k = 0; k < HDIM; k++) acc += R[i][k] * preW[k*HDIM + t];
        T[i][t] = acc;
    }
    __syncthreads();

    for (int i = 0; i < HDIM; i++) {
        float acc = (i == t) ? 1.f : 0.f;
        for (int k = 0; k < HDIM; k++) acc += postW[i*HDIM + k] * T[k][t];
        Meff[i*HDIM + t] = acc;
    }

    {
        float acc = 0.f;
        for (int j = 0; j < HDIM; j++) acc += R[t][j] * preb[j];
        rb[t] = acc;
    }
    __syncthreads();

    float ce = postb[t];
    for (int k = 0; k < HDIM; k++) ce += postW[t*HDIM + k] * rb[k];
    __syncthreads();

    for (int h = 0; h < HEADS; h++) {
        float b = ce;
        for (int j = 0; j < HDIM; j++) b += Meff[t*HDIM + j] * b_in[h*HDIM + j];
        beff[h*HDIM + t] = b;
    }
}

// ============================================================================
// Kernel 2: fold Meff into weights AND split-pack to bf16 hi/lo.
// ============================================================================
__global__ __launch_bounds__(256) void fold_split_kernel(
    const float* __restrict__ W, const float* __restrict__ Meff,
    uint32_t* __restrict__ Wh, uint32_t* __restrict__ Wl)
{
    __shared__ float Ms[HDIM*HDIM];
    const int h  = blockIdx.x;
    const int eb = blockIdx.y;
    const int ep = threadIdx.x & 31;
    const int ig = threadIdx.x >> 5;
    for (int p = threadIdx.x; p < HDIM*HDIM; p += 256) Ms[p] = Meff[p];
    __syncthreads();

    const int e = eb*64 + ep*2;
    float acc[8][2];
    #pragma unroll
    for (int i = 0; i < 8; i++) { acc[i][0] = 0.f; acc[i][1] = 0.f; }

    for (int j = 0; j < HDIM; j++) {
        float2 w = *(const float2*)(W + (size_t)(h*HDIM + j) * E_DIM + e);
        #pragma unroll
        for (int i = 0; i < 8; i++) {
            const float m = Ms[(ig*8 + i)*HDIM + j];
            acc[i][0] += m * w.x;
            acc[i][1] += m * w.y;
        }
    }
    #pragma unroll
    for (int i = 0; i < 8; i++) {
        uint32_t hw, lw;
        split2(acc[i][0], acc[i][1], hw, lw);
        const size_t o = (size_t)(h*HDIM + ig*8 + i) * EW + (e >> 1);
        Wh[o] = hw; Wl[o] = lw;
    }
}

// ============================================================================
// Kernel 3: generic split-pack f32 -> packed bf16 hi/lo.
// ============================================================================
__global__ __launch_bounds__(256) void split_pack_kernel(
    const float* __restrict__ in, uint32_t* __restrict__ hi,
    uint32_t* __restrict__ lo, int nwords)
{
    const int w = blockIdx.x * 256 + threadIdx.x;
    if (w >= nwords) return;
    float2 v = ((const float2*)in)[w];
    uint32_t hw, lw;
    split2(v.x, v.y, hw, lw);
    hi[w] = hw; lo[w] = lw;
}

// ============================================================================
// Kernel 4: bf16x3 GEMM. Same launch/smem config as passing R12 build;
// compensation MMAs reordered into 3 passes (hh, lh, hl) to break the
// per-accumulator RAW chains (ncu: tensor=46%, dependency-limited).
// Per-accumulator update order unchanged (hh->lh->hl) => bit-identical.
// ============================================================================
#define GS 20
#define GB (128*GS)                       // 2560 words per array-buffer

__global__ __launch_bounds__(256) void bf16_gemm_kernel(
    const uint32_t* __restrict__ Ah, const uint32_t* __restrict__ Al,
    const uint32_t* __restrict__ Bh, const uint32_t* __restrict__ Bl,
    const float* __restrict__ bias,
    float* __restrict__ Cf, uint32_t* __restrict__ Ch, uint32_t* __restrict__ Cl,
    int mode)
{
    extern __shared__ uint32_t su[];
    const uint32_t sb = sptr(su);
    const int tid = threadIdx.x;
    const int wid = tid >> 5, lane = tid & 31;
    const int wm = (wid >> 2) * 64, wn = (wid & 3) * 32;
    const int m0 = blockIdx.y * 128, n0 = blockIdx.x * 128;
    const int lr4 = lane >> 2, lc4 = lane & 3;
    const int aR = lane & 15;
    const int aC = (lane & 16) ? 4 : 0;
    const int bR = (lane & 7) + ((lane & 16) ? 8 : 0);
    const int bC = (lane & 8) ? 4 : 0;

    auto load_chunk = [&](int c, int buf) {
        #pragma unroll
        for (int it = 0; it < 2; it++) {
            const int q = tid + it * 256;        // 0..511
            const int row = q >> 2, wc = q & 3;
            const size_t ga = (size_t)(m0 + row) * EW + c*16 + wc*4;
            const size_t gb = (size_t)(n0 + row) * EW + c*16 + wc*4;
            const uint32_t d = (uint32_t)(row*GS + wc*4) * 4;
            cp16(sb + (uint32_t)(0*GB + buf*GB)*4 + d, Ah + ga);
            cp16(sb + (uint32_t)(2*GB + buf*GB)*4 + d, Al + ga);
            cp16(sb + (uint32_t)(4*GB + buf*GB)*4 + d, Bh + gb);
            cp16(sb + (uint32_t)(6*GB + buf*GB)*4 + d, Bl + gb);
        }
    };

    float acc[4][4][4];
    #pragma unroll
    for (int mi = 0; mi < 4; mi++)
        #pragma unroll
        for (int ni = 0; ni < 4; ni++)
            #pragma unroll
            for (int r = 0; r < 4; r++) acc[mi][ni][r] = 0.f;

    load_chunk(0, 0); CP_COMMIT();

    #pragma unroll 1
    for (int c = 0; c < 32; c++) {
        CP_WAIT0();
        __syncthreads();
        if (c < 31) { load_chunk(c + 1, (c + 1) & 1); CP_COMMIT(); }

        const int buf = c & 1;
        const uint32_t bAh = sb + (uint32_t)(buf*GB)*4;
        const uint32_t bAl = sb + (uint32_t)((2+buf)*GB)*4;
        const uint32_t bBh = sb + (uint32_t)((4+buf)*GB)*4;
        const uint32_t bBl = sb + (uint32_t)((6+buf)*GB)*4;

        #pragma unroll
        for (int ks = 0; ks < 2; ks++) {
            uint32_t ah[4][4], al[4][4];
            #pragma unroll
            for (int mi = 0; mi < 4; mi++) {
                const uint32_t off = (uint32_t)((wm + mi*16 + aR)*GS + ks*8 + aC) * 4;
                ldmx4(ah[mi], bAh + off);
                ldmx4(al[mi], bAl + off);
            }
            #pragma unroll
            for (int nb = 0; nb < 2; nb++) {
                uint32_t bh4[4], bl4[4];
                const uint32_t off = (uint32_t)((wn + nb*16 + bR)*GS + ks*8 + bC) * 4;
                ldmx4(bh4, bBh + off);
                ldmx4(bl4, bBl + off);
                // pass-reordered: hh for all 8 accs, then lh, then hl.
                // Per-acc order is still hh->lh->hl (bit-identical result);
                // consecutive updates of the same acc are now 8 MMAs apart.
                #pragma unroll
                for (int pass = 0; pass < 3; pass++) {
                    #pragma unroll
                    for (int h2 = 0; h2 < 2; h2++) {
                        const int ni = nb*2 + h2;
                        #pragma unroll
                        for (int mi = 0; mi < 4; mi++) {
                            const uint32_t* aa = (pass == 1) ? al[mi] : ah[mi];
                            const uint32_t* bb = (pass == 2) ? (bl4 + h2*2)
                                                             : (bh4 + h2*2);
                            mma_bf16(acc[mi][ni], aa, bb);
                        }
                    }
                }
            }
        }
    }

    // ---- epilogue ----
    if (mode == 0) {
        #pragma unroll
        for (int ni = 0; ni < 4; ni++) {
            const int n = n0 + wn + ni*8 + 2*lc4;
            float2 bb = *(const float2*)(bias + n);
            #pragma unroll
            for (int mi = 0; mi < 4; mi++)
                #pragma unroll
                for (int half = 0; half < 2; half++) {
                    const int m = m0 + wm + mi*16 + lr4 + half*8;
                    float2 o;
                    o.x = acc[mi][ni][half*2+0] + bb.x;
                    o.y = acc[mi][ni][half*2+1] + bb.y;
                    *(float2*)(Cf + (size_t)m * E_DIM + n) = o;
                }
        }
    } else if (mode == 1) {
        #pragma unroll
        for (int ni = 0; ni < 4; ni++) {
            const int n = n0 + wn + ni*8 + 2*lc4;
            float2 bb = *(const float2*)(bias + n);
            const int h = n >> 6, dp = (n & 63) >> 1;
            #pragma unroll
            for (int mi = 0; mi < 4; mi++)
                #pragma unroll
                for (int half = 0; half < 2; half++) {
                    const int m = m0 + wm + mi*16 + lr4 + half*8;
                    const int b = m >> 11, s2 = m & 2047;
                    uint32_t hw, lw;
                    split2(acc[mi][ni][half*2+0] + bb.x,
                           acc[mi][ni][half*2+1] + bb.y, hw, lw);
                    const size_t w = ((size_t)(b*HEADS + h) * SEQ + s2) * DW + dp;
                    Ch[w] = hw; Cl[w] = lw;
                }
        }
    } else {
        #pragma unroll
        for (int ni = 0; ni < 4; ni++) {
            const int n = n0 + wn + ni*8 + 2*lc4;
            float2 bb = *(const float2*)(bias + n);
            const int h = n >> 6, dd = n & 63;
            #pragma unroll
            for (int mi = 0; mi < 4; mi++)
                #pragma unroll
                for (int half = 0; half < 2; half++) {
                    const int m = m0 + wm + mi*16 + lr4 + half*8;
                    const int b = m >> 11, s2 = m & 2047;
                    float2 o;
                    o.x = acc[mi][ni][half*2+0] + bb.x;
                    o.y = acc[mi][ni][half*2+1] + bb.y;
                    *(float2*)(Cf + ((size_t)(b*HEADS + h) * SEQ + s2) * HDIM + dd) = o;
                }
        }
    }
}

// ============================================================================
// Kernel 5: transpose+split V: f32 head-major [bh][s][64] -> packed [bh][d][spair]
// ============================================================================
__global__ __launch_bounds__(256) void transpose_split_kernel(
    const float* __restrict__ Vf, uint32_t* __restrict__ Vth,
    uint32_t* __restrict__ Vtl)
{
    __shared__ float ts[64*65];
    const int tid = threadIdx.x;
    const int s0 = blockIdx.x * 64;
    const int bh = blockIdx.y;

    #pragma unroll
    for (int it = 0; it < 4; it++) {
        const int e = tid + it * 256;
        const int s = e >> 4, d4 = (e & 15) * 4;
        float4 v = *(const float4*)(Vf + ((size_t)bh*SEQ + s0 + s) * HDIM + d4);
        ts[s*65 + d4+0] = v.x; ts[s*65 + d4+1] = v.y;
        ts[s*65 + d4+2] = v.z; ts[s*65 + d4+3] = v.w;
    }
    __syncthreads();

    #pragma unroll
    for (int it = 0; it < 8; it++) {
        const int w = tid + it * 256;
        const int d = w >> 5, sp = w & 31;
        uint32_t hw, lw;
        split2(ts[(2*sp)*65 + d], ts[(2*sp+1)*65 + d], hw, lw);
        const size_t o = ((size_t)bh*HDIM + d) * (SEQ/2) + (s0 >> 1) + sp;
        Vth[o] = hw; Vtl[o] = lw;
    }
}

// ============================================================================
// Kernel 6: flash attention (R7 config, MMA pass-reordered). Br=128, Bc=64.
// ============================================================================
#define FS   36
#define FQH  0
#define FQL  4608
#define FKH  9216
#define FKL  13824
#define FVH  18432
#define FVL  23040
#define FBUF 2304
#define FA_WORDS 27648                      // 110592 bytes

__global__ __launch_bounds__(256) void flash_attn_kernel(
    const uint32_t* __restrict__ Qh, const uint32_t* __restrict__ Ql,
    const uint32_t* __restrict__ Kh, const uint32_t* __restrict__ Kl,
    const uint32_t* __restrict__ Vth, const uint32_t* __restrict__ Vtl,
    uint32_t* __restrict__ Oh, uint32_t* __restrict__ Ol)
{
    extern __shared__ uint32_t su[];
    const uint32_t sb = sptr(su);
    const int tid = threadIdx.x;
    const int wid = tid >> 5, lane = tid & 31;
    const int lr4 = lane >> 2, lc4 = lane & 3;
    const int bh = blockIdx.y;
    const int q0 = blockIdx.x * 128;
    const int aR = lane & 15;
    const int aC = (lane & 16) ? 4 : 0;
    const int bR = (lane & 7) + ((lane & 16) ? 8 : 0);
    const int bC = (lane & 8) ? 4 : 0;

    // Q load (once)
    #pragma unroll
    for (int it = 0; it < 4; it++) {
        const int q = tid + it * 256;
        const int row = q >> 3, wc = q & 7;
        const size_t g = ((size_t)bh*SEQ + q0 + row) * DW + wc*4;
        const uint32_t d = (uint32_t)(row*FS + wc*4) * 4;
        cp16(sb + FQH*4 + d, Qh + g);
        cp16(sb + FQL*4 + d, Ql + g);
    }

    auto load_tile = [&](int kt, int buf) {
        const int n0 = kt * 64;
        #pragma unroll
        for (int it = 0; it < 2; it++) {
            const int q = tid + it * 256;
            const int row = q >> 3, wc = q & 7;
            const uint32_t d = (uint32_t)(row*FS + wc*4) * 4;
            const size_t gk = ((size_t)bh*SEQ + n0 + row) * DW + wc*4;
            cp16(sb + (uint32_t)(FKH + buf*FBUF)*4 + d, Kh + gk);
            cp16(sb + (uint32_t)(FKL + buf*FBUF)*4 + d, Kl + gk);
            const size_t gv = ((size_t)bh*HDIM + row) * (SEQ/2) + (n0 >> 1) + wc*4;
            cp16(sb + (uint32_t)(FVH + buf*FBUF)*4 + d, Vth + gv);
            cp16(sb + (uint32_t)(FVL + buf*FBUF)*4 + d, Vtl + gv);
        }
    };

    load_tile(0, 0);
    CP_COMMIT();

    float m0 = -1e30f, m1 = -1e30f, l0r = 0.f, l1r = 0.f;
    float o[8][4];
    #pragma unroll
    for (int ni = 0; ni < 8; ni++)
        #pragma unroll
        for (int r = 0; r < 4; r++) o[ni][r] = 0.f;

    #pragma unroll 1
    for (int kt = 0; kt < SEQ/64; kt++) {
        CP_WAIT0();
        __syncthreads();
        if (kt + 1 < SEQ/64) { load_tile(kt + 1, (kt + 1) & 1); CP_COMMIT(); }
        const int buf = kt & 1;
        const uint32_t bKh = sb + (uint32_t)(FKH + buf*FBUF)*4;
        const uint32_t bKl = sb + (uint32_t)(FKL + buf*FBUF)*4;
        const uint32_t bVh = sb + (uint32_t)(FVH + buf*FBUF)*4;
        const uint32_t bVl = sb + (uint32_t)(FVL + buf*FBUF)*4;

        // S = Q @ K^T  (bf16x3, pass-reordered)
        float s[8][4];
        #pragma unroll
        for (int ni = 0; ni < 8; ni++)
            #pragma unroll
            for (int r = 0; r < 4; r++) s[ni][r] = 0.f;

        #pragma unroll
        for (int ks = 0; ks < 4; ks++) {
            uint32_t ah[4], al[4];
            const uint32_t aoff = (uint32_t)((wid*16 + aR)*FS + ks*8 + aC) * 4;
            ldmx4(ah, sb + FQH*4 + aoff);
            ldmx4(al, sb + FQL*4 + aoff);
            #pragma unroll
            for (int nb = 0; nb < 4; nb++) {
                uint32_t kh4[4], kl4[4];
                const uint32_t boff = (uint32_t)((nb*16 + bR)*FS + ks*8 + bC) * 4;
                ldmx4(kh4, bKh + boff);
                ldmx4(kl4, bKl + boff);
                #pragma unroll
                for (int pass = 0; pass < 3; pass++) {
                    #pragma unroll
                    for (int h2 = 0; h2 < 2; h2++) {
                        const int ni = nb*2 + h2;
                        const uint32_t* aa = (pass == 1) ? al : ah;
                        const uint32_t* bb = (pass == 2) ? (kl4 + h2*2)
                                                         : (kh4 + h2*2);
                        mma_bf16(s[ni], aa, bb);
                    }
                }
            }
        }

        // online softmax (1/8 scale folded in)
        float v0 = -1e30f, v1 = -1e30f;
        #pragma unroll
        for (int ni = 0; ni < 8; ni++) {
            v0 = fmaxf(v0, fmaxf(s[ni][0], s[ni][1]));
            v1 = fmaxf(v1, fmaxf(s[ni][2], s[ni][3]));
        }
        v0 = fmaxf(v0, __shfl_xor_sync(0xffffffffu, v0, 1));
        v0 = fmaxf(v0, __shfl_xor_sync(0xffffffffu, v0, 2));
        v1 = fmaxf(v1, __shfl_xor_sync(0xffffffffu, v1, 1));
        v1 = fmaxf(v1, __shfl_xor_sync(0xffffffffu, v1, 2));
        const float mn0 = fmaxf(m0, 0.125f * v0), mn1 = fmaxf(m1, 0.125f * v1);
        const float al0 = __expf(m0 - mn0), al1 = __expf(m1 - mn1);
        m0 = mn0; m1 = mn1;

        float rs0 = 0.f, rs1 = 0.f;
        #pragma unroll
        for (int ni = 0; ni < 8; ni++) {
            s[ni][0] = __expf(fmaf(s[ni][0], 0.125f, -mn0));
            s[ni][1] = __expf(fmaf(s[ni][1], 0.125f, -mn0));
            s[ni][2] = __expf(fmaf(s[ni][2], 0.125f, -mn1));
            s[ni][3] = __expf(fmaf(s[ni][3], 0.125f, -mn1));
            rs0 += s[ni][0] + s[ni][1];
            rs1 += s[ni][2] + s[ni][3];
        }
        rs0 += __shfl_xor_sync(0xffffffffu, rs0, 1);
        rs0 += __shfl_xor_sync(0xffffffffu, rs0, 2);
        rs1 += __shfl_xor_sync(0xffffffffu, rs1, 1);
        rs1 += __shfl_xor_sync(0xffffffffu, rs1, 2);
        l0r = l0r * al0 + rs0;
        l1r = l1r * al1 + rs1;
        #pragma unroll
        for (int ni = 0; ni < 8; ni++) {
            o[ni][0] *= al0; o[ni][1] *= al0;
            o[ni][2] *= al1; o[ni][3] *= al1;
        }

        // O += P @ V  (pass-reordered; P fragments from registers)
        #pragma unroll
        for (int b = 0; b < 4; b++) {
            uint32_t ph[4], pl[4];
            split2(s[2*b][0],   s[2*b][1],   ph[0], pl[0]);
            split2(s[2*b][2],   s[2*b][3],   ph[1], pl[1]);
            split2(s[2*b+1][0], s[2*b+1][1], ph[2], pl[2]);
            split2(s[2*b+1][2], s[2*b+1][3], ph[3], pl[3]);
            #pragma unroll
            for (int nb = 0; nb < 4; nb++) {
                uint32_t vh4[4], vl4[4];
                const uint32_t voff = (uint32_t)((nb*16 + bR)*FS + b*8 + bC) * 4;
                ldmx4(vh4, bVh + voff);
                ldmx4(vl4, bVl + voff);
                #pragma unroll
                for (int pass = 0; pass < 3; pass++) {
                    #pragma unroll
                    for (int h2 = 0; h2 < 2; h2++) {
                        const int ni = nb*2 + h2;
                        const uint32_t* aa = (pass == 1) ? pl : ph;
                        const uint32_t* bb = (pass == 2) ? (vl4 + h2*2)
                                                         : (vh4 + h2*2);
                        mma_bf16(o[ni], aa, bb);
                    }
                }
            }
        }
    }

    // epilogue: normalize, split-pack, write [b*S+s][epair]
    const int b = bh >> 4, h = bh & 15;
    const float inv0 = 1.f / l0r, inv1 = 1.f / l1r;
    const int rA = wid*16 + lr4;
    #pragma unroll
    for (int ni = 0; ni < 8; ni++) {
        const int ep = (h*HDIM + ni*8 + 2*lc4) >> 1;
        uint32_t hw, lw;
        split2(o[ni][0]*inv0, o[ni][1]*inv0, hw, lw);
        size_t w = ((size_t)b*SEQ + q0 + rA) * EW + ep;
        Oh[w] = hw; Ol[w] = lw;
        split2(o[ni][2]*inv1, o[ni][3]*inv1, hw, lw);
        w = ((size_t)b*SEQ + q0 + rA + 8) * EW + ep;
        Oh[w] = hw; Ol[w] = lw;
    }
}

// ============================================================================
// Host launcher — V-GEMM as launch #4 so ncu's capture window hits it.
// ============================================================================
extern "C" void kernel_launch(void* const* d_in, const int* in_sizes, int n_in,
                              void* d_out, int out_size)
{
    (void)in_sizes; (void)n_in; (void)out_size;

    const float* query   = (const float*)d_in[0];
    const float* key     = (const float*)d_in[1];
    const float* value   = (const float*)d_in[2];
    const float* wq      = (const float*)d_in[3];
    const float* bq      = (const float*)d_in[4];
    const float* wk      = (const float*)d_in[5];
    const float* bk      = (const float*)d_in[6];
    const float* wv      = (const float*)d_in[7];
    const float* bv      = (const float*)d_in[8];
    const float* wo      = (const float*)d_in[9];
    const float* bo      = (const float*)d_in[10];
    const float* q_theta = (const float*)d_in[11];
    const float* q_phi   = (const float*)d_in[12];
    const float* q_preW  = (const float*)d_in[13];
    const float* q_preb  = (const float*)d_in[14];
    const float* q_postW = (const float*)d_in[15];
    const float* q_postb = (const float*)d_in[16];
    const float* k_theta = (const float*)d_in[17];
    const float* k_phi   = (const float*)d_in[18];
    const float* k_preW  = (const float*)d_in[19];
    const float* k_preb  = (const float*)d_in[20];
    const float* k_postW = (const float*)d_in[21];
    const float* k_postb = (const float*)d_in[22];
    float* out = (float*)d_out;

    float *pMq, *pMk, *pbq, *pbk, *pVf;
    uint32_t *pWqh, *pWql, *pWkh, *pWkl, *pWvh, *pWvl, *pWoh, *pWol;
    uint32_t *pXqh, *pXql, *pXkh, *pXkl, *pXvh, *pXvl;
    uint32_t *pQh, *pQl, *pKh, *pKl, *pVth, *pVtl, *pOh, *pOl;
    cudaGetSymbolAddress((void**)&pMq, g_Mq);
    cudaGetSymbolAddress((void**)&pMk, g_Mk);
    cudaGetSymbolAddress((void**)&pbq, g_bq);
    cudaGetSymbolAddress((void**)&pbk, g_bk);
    cudaGetSymbolAddress((void**)&pWqh, g_Wqh);
    cudaGetSymbolAddress((void**)&pWql, g_Wql);
    cudaGetSymbolAddress((void**)&pWkh, g_Wkh);
    cudaGetSymbolAddress((void**)&pWkl, g_Wkl);
    cudaGetSymbolAddress((void**)&pWvh, g_Wvh);
    cudaGetSymbolAddress((void**)&pWvl, g_Wvl);
    cudaGetSymbolAddress((void**)&pWoh, g_Woh);
    cudaGetSymbolAddress((void**)&pWol, g_Wol);
    cudaGetSymbolAddress((void**)&pXqh, g_Xqh);
    cudaGetSymbolAddress((void**)&pXql, g_Xql);
    cudaGetSymbolAddress((void**)&pXkh, g_Xkh);
    cudaGetSymbolAddress((void**)&pXkl, g_Xkl);
    cudaGetSymbolAddress((void**)&pXvh, g_Xvh);
    cudaGetSymbolAddress((void**)&pXvl, g_Xvl);
    cudaGetSymbolAddress((void**)&pQh, g_Qh);
    cudaGetSymbolAddress((void**)&pQl, g_Ql);
    cudaGetSymbolAddress((void**)&pKh, g_Kh);
    cudaGetSymbolAddress((void**)&pKl, g_Kl);
    cudaGetSymbolAddress((void**)&pVf, g_Vf);
    cudaGetSymbolAddress((void**)&pVth, g_Vth);
    cudaGetSymbolAddress((void**)&pVtl, g_Vtl);
    cudaGetSymbolAddress((void**)&pOh, g_Oh);
    cudaGetSymbolAddress((void**)&pOl, g_Ol);

    const int gemm_smem = 8 * GB * (int)sizeof(uint32_t);   // 81920
    cudaFuncSetAttribute(bf16_gemm_kernel,
                         cudaFuncAttributeMaxDynamicSharedMemorySize, gemm_smem);
    const int fa_smem = FA_WORDS * (int)sizeof(uint32_t);   // 110592
    cudaFuncSetAttribute(flash_attn_kernel,
                         cudaFuncAttributeMaxDynamicSharedMemorySize, fa_smem);
    dim3 ggrid(E_DIM/128, ROWS/128);

    // Launch 1-3: V-GEMM prerequisites (+ one independent small kernel)
    split_pack_kernel<<<(ROWS*EW)/256, 256>>>(value, pXvh, pXvl, ROWS*EW);
    split_pack_kernel<<<(E_DIM*EW)/256, 256>>>(wv, pWvh, pWvl, E_DIM*EW);
    build_eff_kernel<<<1, 64>>>(q_theta, q_phi, q_preW, q_preb, q_postW, q_postb,
                                bq, pMq, pbq);

    // Launch 4: V projection (ncu capture target)
    bf16_gemm_kernel<<<ggrid, 256, gemm_smem>>>(pXvh, pXvl, pWvh, pWvl, bv,
                                                pVf, nullptr, nullptr, 2);

    // Remaining preprocessing
    build_eff_kernel<<<1, 64>>>(k_theta, k_phi, k_preW, k_preb, k_postW, k_postb,
                                bk, pMk, pbk);
    fold_split_kernel<<<dim3(HEADS, 16), 256>>>(wq, pMq, pWqh, pWql);
    fold_split_kernel<<<dim3(HEADS, 16), 256>>>(wk, pMk, pWkh, pWkl);
    split_pack_kernel<<<(E_DIM*EW)/256, 256>>>(wo, pWoh, pWol, E_DIM*EW);
    split_pack_kernel<<<(ROWS*EW)/256, 256>>>(query, pXqh, pXql, ROWS*EW);
    split_pack_kernel<<<(ROWS*EW)/256, 256>>>(key,   pXkh, pXkl, ROWS*EW);

    // Q/K projections
    bf16_gemm_kernel<<<ggrid, 256, gemm_smem>>>(pXqh, pXql, pWqh, pWql, pbq,
                                                nullptr, pQh, pQl, 1);
    bf16_gemm_kernel<<<ggrid, 256, gemm_smem>>>(pXkh, pXkl, pWkh, pWkl, pbk,
                                                nullptr, pKh, pKl, 1);

    // V transpose+split
    transpose_split_kernel<<<dim3(SEQ/64, BATCH*HEADS), 256>>>(pVf, pVth, pVtl);

    // flash attention
    flash_attn_kernel<<<dim3(SEQ/128, BATCH*HEADS), 256, fa_smem>>>(
        pQh, pQl, pKh, pKl, pVth, pVtl, pOh, pOl);

    // output projection
    bf16_gemm_kernel<<<ggrid, 256, gemm_smem>>>(pOh, pOl, pWoh, pWol, bo,
                                                out, nullptr, nullptr, 0);
}

// round 15
// speedup vs baseline: 1.0215x; 1.0215x over previous
#include <cuda_runtime.h>
#include <cuda_bf16.h>
#include <cstdint>

// Problem constants
#define E_DIM   1024
#define HEADS   16
#define HDIM    64
#define BATCH   4
#define SEQ     2048
#define ROWS    (BATCH*SEQ)        // 8192
#define NQUBITS 6
#define EW      (E_DIM/2)          // 512 packed words per E row
#define DW      (HDIM/2)           // 32 packed words per head row

// ---------------- helpers ----------------
__device__ __forceinline__ void mma_bf16(
    float* d, const uint32_t* a, const uint32_t* b)
{
    asm volatile(
        "mma.sync.aligned.m16n8k16.row.col.f32.bf16.bf16.f32 "
        "{%0,%1,%2,%3}, {%4,%5,%6,%7}, {%8,%9}, {%0,%1,%2,%3};"
        : "+f"(d[0]), "+f"(d[1]), "+f"(d[2]), "+f"(d[3])
        : "r"(a[0]), "r"(a[1]), "r"(a[2]), "r"(a[3]), "r"(b[0]), "r"(b[1]));
}
__device__ __forceinline__ void split2(float x, float y,
                                       uint32_t& hw, uint32_t& lw)
{
    __nv_bfloat16 hx = __float2bfloat16(x);
    __nv_bfloat16 hy = __float2bfloat16(y);
    __nv_bfloat162 h2; h2.x = hx; h2.y = hy;
    __nv_bfloat162 l2;
    l2.x = __float2bfloat16(x - __bfloat162float(hx));
    l2.y = __float2bfloat16(y - __bfloat162float(hy));
    hw = *reinterpret_cast<uint32_t*>(&h2);
    lw = *reinterpret_cast<uint32_t*>(&l2);
}
__device__ __forceinline__ uint32_t sptr(const void* p) {
    return (uint32_t)__cvta_generic_to_shared(p);
}
__device__ __forceinline__ void cp16(uint32_t dst, const void* src) {
    asm volatile("cp.async.cg.shared.global [%0], [%1], 16;" :: "r"(dst), "l"(src));
}
#define CP_COMMIT() asm volatile("cp.async.commit_group;" ::: "memory")
#define CP_WAIT0()  asm volatile("cp.async.wait_group 0;" ::: "memory")
__device__ __forceinline__ void ldmx4(uint32_t* r, uint32_t addr) {
    asm volatile("ldmatrix.sync.aligned.m8n8.x4.shared.b16 {%0,%1,%2,%3}, [%4];"
        : "=r"(r[0]), "=r"(r[1]), "=r"(r[2]), "=r"(r[3]) : "r"(addr));
}

// ---------------- device scratch ----------------
__device__ float    g_Mq[HDIM*HDIM];
__device__ float    g_Mk[HDIM*HDIM];
__device__ float    g_bq[E_DIM];
__device__ float    g_bk[E_DIM];
__device__ uint32_t g_Wqh[E_DIM*EW], g_Wql[E_DIM*EW];
__device__ uint32_t g_Wkh[E_DIM*EW], g_Wkl[E_DIM*EW];
__device__ uint32_t g_Wvh[E_DIM*EW], g_Wvl[E_DIM*EW];
__device__ uint32_t g_Woh[E_DIM*EW], g_Wol[E_DIM*EW];
__device__ uint32_t g_Xqh[(size_t)ROWS*EW], g_Xql[(size_t)ROWS*EW];
__device__ uint32_t g_Xkh[(size_t)ROWS*EW], g_Xkl[(size_t)ROWS*EW];
__device__ uint32_t g_Xvh[(size_t)ROWS*EW], g_Xvl[(size_t)ROWS*EW];
__device__ uint32_t g_Qh[(size_t)ROWS*EW],  g_Ql[(size_t)ROWS*EW];
__device__ uint32_t g_Kh[(size_t)ROWS*EW],  g_Kl[(size_t)ROWS*EW];
__device__ float    g_Vf[(size_t)ROWS*E_DIM];
__device__ uint32_t g_Vth[(size_t)64*HDIM*(SEQ/2)], g_Vtl[(size_t)64*HDIM*(SEQ/2)];
__device__ uint32_t g_Oh[(size_t)ROWS*EW],  g_Ol[(size_t)ROWS*EW];

// ============================================================================
// Kernel 1: build effective quantum operator (tiny, exact fp32).
// ============================================================================
__global__ void build_eff_kernel(
    const float* __restrict__ theta, const float* __restrict__ phi,
    const float* __restrict__ preW,  const float* __restrict__ preb,
    const float* __restrict__ postW, const float* __restrict__ postb,
    const float* __restrict__ b_in,
    float* __restrict__ Meff, float* __restrict__ beff)
{
    __shared__ float R[HDIM][HDIM];
    __shared__ float T[HDIM][HDIM];
    __shared__ float rb[HDIM];
    __shared__ float ctb[NQUBITS], stb[NQUBITS], cpb[NQUBITS];

    const int t = threadIdx.x;
    if (t < NQUBITS) {
        ctb[t] = cosf(theta[t]);
        stb[t] = sinf(theta[t]);
        cpb[t] = cosf(phi[t]);
    }
    __syncthreads();

    float v[HDIM];
    for (int i = 0; i < HDIM; i++) v[i] = (i == t) ? 1.f : 0.f;
    for (int q = 0; q < NQUBITS; q++) {
        const int mask = 1 << q;
        const float c = ctb[q], s = stb[q], p = cpb[q];
        for (int i0 = 0; i0 < HDIM; i0++) {
            if (i0 & mask) continue;
            const int i1 = i0 | mask;
            float x0 = v[i0], x1 = v[i1];
            v[i0] = c * x0 - s * x1;
            v[i1] = (s * x0 + c * x1) * p;
        }
    }
    for (int i = 0; i < HDIM; i++) R[i][t] = v[i];
    __syncthreads();

    for (int i = 0; i < HDIM; i++) {
        float acc = 0.f;
        for (int k = 0; k < HDIM; k++) acc += R[i][k] * preW[k*HDIM + t];
        T[i][t] = acc;
    }
    __syncthreads();

    for (int i = 0; i < HDIM; i++) {
        float acc = (i == t) ? 1.f : 0.f;
        for (int k = 0; k < HDIM; k++) acc += postW[i*HDIM + k] * T[k][t];
        Meff[i*HDIM + t] = acc;
    }

    {
        float acc = 0.f;
        for (int j = 0; j < HDIM; j++) acc += R[t][j] * preb[j];
        rb[t] = acc;
    }
    __syncthreads();

    float ce = postb[t];
    for (int k = 0; k < HDIM; k++) ce += postW[t*HDIM + k] * rb[k];
    __syncthreads();

    for (int h = 0; h < HEADS; h++) {
        float b = ce;
        for (int j = 0; j < HDIM; j++) b += Meff[t*HDIM + j] * b_in[h*HDIM + j];
        beff[h*HDIM + t] = b;
    }
}

// ============================================================================
// Kernel 2: fold Meff into weights AND split-pack to bf16 hi/lo.
// ============================================================================
__global__ __launch_bounds__(256) void fold_split_kernel(
    const float* __restrict__ W, const float* __restrict__ Meff,
    uint32_t* __restrict__ Wh, uint32_t* __restrict__ Wl)
{
    __shared__ float Ms[HDIM*HDIM];
    const int h  = blockIdx.x;
    const int eb = blockIdx.y;
    const int ep = threadIdx.x & 31;
    const int ig = threadIdx.x >> 5;
    for (int p = threadIdx.x; p < HDIM*HDIM; p += 256) Ms[p] = Meff[p];
    __syncthreads();

    const int e = eb*64 + ep*2;
    float acc[8][2];
    #pragma unroll
    for (int i = 0; i < 8; i++) { acc[i][0] = 0.f; acc[i][1] = 0.f; }

    for (int j = 0; j < HDIM; j++) {
        float2 w = *(const float2*)(W + (size_t)(h*HDIM + j) * E_DIM + e);
        #pragma unroll
        for (int i = 0; i < 8; i++) {
            const float m = Ms[(ig*8 + i)*HDIM + j];
            acc[i][0] += m * w.x;
            acc[i][1] += m * w.y;
        }
    }
    #pragma unroll
    for (int i = 0; i < 8; i++) {
        uint32_t hw, lw;
        split2(acc[i][0], acc[i][1], hw, lw);
        const size_t o = (size_t)(h*HDIM + ig*8 + i) * EW + (e >> 1);
        Wh[o] = hw; Wl[o] = lw;
    }
}

// ============================================================================
// Kernel 3: generic split-pack f32 -> packed bf16 hi/lo.
// ============================================================================
__global__ __launch_bounds__(256) void split_pack_kernel(
    const float* __restrict__ in, uint32_t* __restrict__ hi,
    uint32_t* __restrict__ lo, int nwords)
{
    const int w = blockIdx.x * 256 + threadIdx.x;
    if (w >= nwords) return;
    float2 v = ((const float2*)in)[w];
    uint32_t hw, lw;
    split2(v.x, v.y, hw, lw);
    hi[w] = hw; lo[w] = lw;
}

// ============================================================================
// Kernel 4: bf16x3 GEMM, 512 threads / 16 warps, warp tile 32x32 (4x4 grid
// over the same 128x128 CTA tile). Same smem layout/size as passing build.
// Per-thread accs halve (64->32 floats) -> ~85 regs -> 4 warps/SMSP to cover
// ldmatrix latency (ncu R13: tensor=46%, latency-limited at 2 warps/SMSP).
// Per-accumulator accumulation order unchanged => bit-identical results.
// ============================================================================
#define GS 20
#define GB (128*GS)                       // 2560 words per array-buffer

__global__ __launch_bounds__(512) void bf16_gemm_kernel(
    const uint32_t* __restrict__ Ah, const uint32_t* __restrict__ Al,
    const uint32_t* __restrict__ Bh, const uint32_t* __restrict__ Bl,
    const float* __restrict__ bias,
    float* __restrict__ Cf, uint32_t* __restrict__ Ch, uint32_t* __restrict__ Cl,
    int mode)
{
    extern __shared__ uint32_t su[];
    const uint32_t sb = sptr(su);
    const int tid = threadIdx.x;
    const int wid = tid >> 5, lane = tid & 31;
    const int wm = (wid >> 2) * 32, wn = (wid & 3) * 32;   // 4x4 warp grid
    const int m0 = blockIdx.y * 128, n0 = blockIdx.x * 128;
    const int lr4 = lane >> 2, lc4 = lane & 3;
    const int aR = lane & 15;
    const int aC = (lane & 16) ? 4 : 0;
    const int bR = (lane & 7) + ((lane & 16) ? 8 : 0);
    const int bC = (lane & 8) ? 4 : 0;

    // one cp16 per thread per array per chunk (512 threads x 4B words x 4)
    auto load_chunk = [&](int c, int buf) {
        const int row = tid >> 2, wc = tid & 3;
        const size_t ga = (size_t)(m0 + row) * EW + c*16 + wc*4;
        const size_t gb = (size_t)(n0 + row) * EW + c*16 + wc*4;
        const uint32_t d = (uint32_t)(row*GS + wc*4) * 4;
        cp16(sb + (uint32_t)(0*GB + buf*GB)*4 + d, Ah + ga);
        cp16(sb + (uint32_t)(2*GB + buf*GB)*4 + d, Al + ga);
        cp16(sb + (uint32_t)(4*GB + buf*GB)*4 + d, Bh + gb);
        cp16(sb + (uint32_t)(6*GB + buf*GB)*4 + d, Bl + gb);
    };

    float acc[2][4][4];
    #pragma unroll
    for (int mi = 0; mi < 2; mi++)
        #pragma unroll
        for (int ni = 0; ni < 4; ni++)
            #pragma unroll
            for (int r = 0; r < 4; r++) acc[mi][ni][r] = 0.f;

    load_chunk(0, 0); CP_COMMIT();

    #pragma unroll 1
    for (int c = 0; c < 32; c++) {
        CP_WAIT0();
        __syncthreads();
        if (c < 31) { load_chunk(c + 1, (c + 1) & 1); CP_COMMIT(); }

        const int buf = c & 1;
        const uint32_t bAh = sb + (uint32_t)(buf*GB)*4;
        const uint32_t bAl = sb + (uint32_t)((2+buf)*GB)*4;
        const uint32_t bBh = sb + (uint32_t)((4+buf)*GB)*4;
        const uint32_t bBl = sb + (uint32_t)((6+buf)*GB)*4;

        #pragma unroll
        for (int ks = 0; ks < 2; ks++) {
            uint32_t ah[2][4], al[2][4];
            #pragma unroll
            for (int mi = 0; mi < 2; mi++) {
                const uint32_t off = (uint32_t)((wm + mi*16 + aR)*GS + ks*8 + aC) * 4;
                ldmx4(ah[mi], bAh + off);
                ldmx4(al[mi], bAl + off);
            }
            #pragma unroll
            for (int nb = 0; nb < 2; nb++) {
                uint32_t bh4[4], bl4[4];
                const uint32_t off = (uint32_t)((wn + nb*16 + bR)*GS + ks*8 + bC) * 4;
                ldmx4(bh4, bBh + off);
                ldmx4(bl4, bBl + off);
                #pragma unroll
                for (int pass = 0; pass < 3; pass++) {
                    #pragma unroll
                    for (int h2 = 0; h2 < 2; h2++) {
                        const int ni = nb*2 + h2;
                        #pragma unroll
                        for (int mi = 0; mi < 2; mi++) {
                            const uint32_t* aa = (pass == 1) ? al[mi] : ah[mi];
                            const uint32_t* bb = (pass == 2) ? (bl4 + h2*2)
                                                             : (bh4 + h2*2);
                            mma_bf16(acc[mi][ni], aa, bb);
                        }
                    }
                }
            }
        }
    }

    // ---- epilogue ----
    if (mode == 0) {
        #pragma unroll
        for (int ni = 0; ni < 4; ni++) {
            const int n = n0 + wn + ni*8 + 2*lc4;
            float2 bb = *(const float2*)(bias + n);
            #pragma unroll
            for (int mi = 0; mi < 2; mi++)
                #pragma unroll
                for (int half = 0; half < 2; half++) {
                    const int m = m0 + wm + mi*16 + lr4 + half*8;
                    float2 o;
                    o.x = acc[mi][ni][half*2+0] + bb.x;
                    o.y = acc[mi][ni][half*2+1] + bb.y;
                    *(float2*)(Cf + (size_t)m * E_DIM + n) = o;
                }
        }
    } else if (mode == 1) {
        #pragma unroll
        for (int ni = 0; ni < 4; ni++) {
            const int n = n0 + wn + ni*8 + 2*lc4;
            float2 bb = *(const float2*)(bias + n);
            const int h = n >> 6, dp = (n & 63) >> 1;
            #pragma unroll
            for (int mi = 0; mi < 2; mi++)
                #pragma unroll
                for (int half = 0; half < 2; half++) {
                    const int m = m0 + wm + mi*16 + lr4 + half*8;
                    const int b = m >> 11, s2 = m & 2047;
                    uint32_t hw, lw;
                    split2(acc[mi][ni][half*2+0] + bb.x,
                           acc[mi][ni][half*2+1] + bb.y, hw, lw);
                    const size_t w = ((size_t)(b*HEADS + h) * SEQ + s2) * DW + dp;
                    Ch[w] = hw; Cl[w] = lw;
                }
        }
    } else {
        #pragma unroll
        for (int ni = 0; ni < 4; ni++) {
            const int n = n0 + wn + ni*8 + 2*lc4;
            float2 bb = *(const float2*)(bias + n);
            const int h = n >> 6, dd = n & 63;
            #pragma unroll
            for (int mi = 0; mi < 2; mi++)
                #pragma unroll
                for (int half = 0; half < 2; half++) {
                    const int m = m0 + wm + mi*16 + lr4 + half*8;
                    const int b = m >> 11, s2 = m & 2047;
                    float2 o;
                    o.x = acc[mi][ni][half*2+0] + bb.x;
                    o.y = acc[mi][ni][half*2+1] + bb.y;
                    *(float2*)(Cf + ((size_t)(b*HEADS + h) * SEQ + s2) * HDIM + dd) = o;
                }
        }
    }
}

// ============================================================================
// Kernel 5: transpose+split V: f32 head-major [bh][s][64] -> packed [bh][d][spair]
// ============================================================================
__global__ __launch_bounds__(256) void transpose_split_kernel(
    const float* __restrict__ Vf, uint32_t* __restrict__ Vth,
    uint32_t* __restrict__ Vtl)
{
    __shared__ float ts[64*65];
    const int tid = threadIdx.x;
    const int s0 = blockIdx.x * 64;
    const int bh = blockIdx.y;

    #pragma unroll
    for (int it = 0; it < 4; it++) {
        const int e = tid + it * 256;
        const int s = e >> 4, d4 = (e & 15) * 4;
        float4 v = *(const float4*)(Vf + ((size_t)bh*SEQ + s0 + s) * HDIM + d4);
        ts[s*65 + d4+0] = v.x; ts[s*65 + d4+1] = v.y;
        ts[s*65 + d4+2] = v.z; ts[s*65 + d4+3] = v.w;
    }
    __syncthreads();

    #pragma unroll
    for (int it = 0; it < 8; it++) {
        const int w = tid + it * 256;
        const int d = w >> 5, sp = w & 31;
        uint32_t hw, lw;
        split2(ts[(2*sp)*65 + d], ts[(2*sp+1)*65 + d], hw, lw);
        const size_t o = ((size_t)bh*HDIM + d) * (SEQ/2) + (s0 >> 1) + sp;
        Vth[o] = hw; Vtl[o] = lw;
    }
}

// ============================================================================
// Kernel 6: flash attention (R7 passing config, unchanged). Br=128, Bc=64.
// ============================================================================
#define FS   36
#define FQH  0
#define FQL  4608
#define FKH  9216
#define FKL  13824
#define FVH  18432
#define FVL  23040
#define FBUF 2304
#define FA_WORDS 27648                      // 110592 bytes

__global__ __launch_bounds__(256) void flash_attn_kernel(
    const uint32_t* __restrict__ Qh, const uint32_t* __restrict__ Ql,
    const uint32_t* __restrict__ Kh, const uint32_t* __restrict__ Kl,
    const uint32_t* __restrict__ Vth, const uint32_t* __restrict__ Vtl,
    uint32_t* __restrict__ Oh, uint32_t* __restrict__ Ol)
{
    extern __shared__ uint32_t su[];
    const uint32_t sb = sptr(su);
    const int tid = threadIdx.x;
    const int wid = tid >> 5, lane = tid & 31;
    const int lr4 = lane >> 2, lc4 = lane & 3;
    const int bh = blockIdx.y;
    const int q0 = blockIdx.x * 128;
    const int aR = lane & 15;
    const int aC = (lane & 16) ? 4 : 0;
    const int bR = (lane & 7) + ((lane & 16) ? 8 : 0);
    const int bC = (lane & 8) ? 4 : 0;

    // Q load (once)
    #pragma unroll
    for (int it = 0; it < 4; it++) {
        const int q = tid + it * 256;
        const int row = q >> 3, wc = q & 7;
        const size_t g = ((size_t)bh*SEQ + q0 + row) * DW + wc*4;
        const uint32_t d = (uint32_t)(row*FS + wc*4) * 4;
        cp16(sb + FQH*4 + d, Qh + g);
        cp16(sb + FQL*4 + d, Ql + g);
    }

    auto load_tile = [&](int kt, int buf) {
        const int n0 = kt * 64;
        #pragma unroll
        for (int it = 0; it < 2; it++) {
            const int q = tid + it * 256;
            const int row = q >> 3, wc = q & 7;
            const uint32_t d = (uint32_t)(row*FS + wc*4) * 4;
            const size_t gk = ((size_t)bh*SEQ + n0 + row) * DW + wc*4;
            cp16(sb + (uint32_t)(FKH + buf*FBUF)*4 + d, Kh + gk);
            cp16(sb + (uint32_t)(FKL + buf*FBUF)*4 + d, Kl + gk);
            const size_t gv = ((size_t)bh*HDIM + row) * (SEQ/2) + (n0 >> 1) + wc*4;
            cp16(sb + (uint32_t)(FVH + buf*FBUF)*4 + d, Vth + gv);
            cp16(sb + (uint32_t)(FVL + buf*FBUF)*4 + d, Vtl + gv);
        }
    };

    load_tile(0, 0);
    CP_COMMIT();

    float m0 = -1e30f, m1 = -1e30f, l0r = 0.f, l1r = 0.f;
    float o[8][4];
    #pragma unroll
    for (int ni = 0; ni < 8; ni++)
        #pragma unroll
        for (int r = 0; r < 4; r++) o[ni][r] = 0.f;

    #pragma unroll 1
    for (int kt = 0; kt < SEQ/64; kt++) {
        CP_WAIT0();
        __syncthreads();
        if (kt + 1 < SEQ/64) { load_tile(kt + 1, (kt + 1) & 1); CP_COMMIT(); }
        const int buf = kt & 1;
        const uint32_t bKh = sb + (uint32_t)(FKH + buf*FBUF)*4;
        const uint32_t bKl = sb + (uint32_t)(FKL + buf*FBUF)*4;
        const uint32_t bVh = sb + (uint32_t)(FVH + buf*FBUF)*4;
        const uint32_t bVl = sb + (uint32_t)(FVL + buf*FBUF)*4;

        // S = Q @ K^T  (bf16x3)
        float s[8][4];
        #pragma unroll
        for (int ni = 0; ni < 8; ni++)
            #pragma unroll
            for (int r = 0; r < 4; r++) s[ni][r] = 0.f;

        #pragma unroll
        for (int ks = 0; ks < 4; ks++) {
            uint32_t ah[4], al[4];
            const uint32_t aoff = (uint32_t)((wid*16 + aR)*FS + ks*8 + aC) * 4;
            ldmx4(ah, sb + FQH*4 + aoff);
            ldmx4(al, sb + FQL*4 + aoff);
            #pragma unroll
            for (int nb = 0; nb < 4; nb++) {
                uint32_t kh4[4], kl4[4];
                const uint32_t boff = (uint32_t)((nb*16 + bR)*FS + ks*8 + bC) * 4;
                ldmx4(kh4, bKh + boff);
                ldmx4(kl4, bKl + boff);
                #pragma unroll
                for (int h2 = 0; h2 < 2; h2++) {
                    const int ni = nb*2 + h2;
                    mma_bf16(s[ni], ah, kh4 + h2*2);
                    mma_bf16(s[ni], al, kh4 + h2*2);
                    mma_bf16(s[ni], ah, kl4 + h2*2);
                }
            }
        }

        // online softmax (1/8 scale folded in)
        float v0 = -1e30f, v1 = -1e30f;
        #pragma unroll
        for (int ni = 0; ni < 8; ni++) {
            v0 = fmaxf(v0, fmaxf(s[ni][0], s[ni][1]));
            v1 = fmaxf(v1, fmaxf(s[ni][2], s[ni][3]));
        }
        v0 = fmaxf(v0, __shfl_xor_sync(0xffffffffu, v0, 1));
        v0 = fmaxf(v0, __shfl_xor_sync(0xffffffffu, v0, 2));
        v1 = fmaxf(v1, __shfl_xor_sync(0xffffffffu, v1, 1));
        v1 = fmaxf(v1, __shfl_xor_sync(0xffffffffu, v1, 2));
        const float mn0 = fmaxf(m0, 0.125f * v0), mn1 = fmaxf(m1, 0.125f * v1);
        const float al0 = __expf(m0 - mn0), al1 = __expf(m1 - mn1);
        m0 = mn0; m1 = mn1;

        float rs0 = 0.f, rs1 = 0.f;
        #pragma unroll
        for (int ni = 0; ni < 8; ni++) {
            s[ni][0] = __expf(fmaf(s[ni][0], 0.125f, -mn0));
            s[ni][1] = __expf(fmaf(s[ni][1], 0.125f, -mn0));
            s[ni][2] = __expf(fmaf(s[ni][2], 0.125f, -mn1));
            s[ni][3] = __expf(fmaf(s[ni][3], 0.125f, -mn1));
            rs0 += s[ni][0] + s[ni][1];
            rs1 += s[ni][2] + s[ni][3];
        }
        rs0 += __shfl_xor_sync(0xffffffffu, rs0, 1);
        rs0 += __shfl_xor_sync(0xffffffffu, rs0, 2);
        rs1 += __shfl_xor_sync(0xffffffffu, rs1, 1);
        rs1 += __shfl_xor_sync(0xffffffffu, rs1, 2);
        l0r = l0r * al0 + rs0;
        l1r = l1r * al1 + rs1;
        #pragma unroll
        for (int ni = 0; ni < 8; ni++) {
            o[ni][0] *= al0; o[ni][1] *= al0;
            o[ni][2] *= al1; o[ni][3] *= al1;
        }

        // O += P @ V  (P fragments directly from registers)
        #pragma unroll
        for (int b = 0; b < 4; b++) {
            uint32_t ph[4], pl[4];
            split2(s[2*b][0],   s[2*b][1],   ph[0], pl[0]);
            split2(s[2*b][2],   s[2*b][3],   ph[1], pl[1]);
            split2(s[2*b+1][0], s[2*b+1][1], ph[2], pl[2]);
            split2(s[2*b+1][2], s[2*b+1][3], ph[3], pl[3]);
            #pragma unroll
            for (int nb = 0; nb < 4; nb++) {
                uint32_t vh4[4], vl4[4];
                const uint32_t voff = (uint32_t)((nb*16 + bR)*FS + b*8 + bC) * 4;
                ldmx4(vh4, bVh + voff);
                ldmx4(vl4, bVl + voff);
                #pragma unroll
                for (int h2 = 0; h2 < 2; h2++) {
                    const int ni = nb*2 + h2;
                    mma_bf16(o[ni], ph, vh4 + h2*2);
                    mma_bf16(o[ni], pl, vh4 + h2*2);
                    mma_bf16(o[ni], ph, vl4 + h2*2);
                }
            }
        }
    }

    // epilogue: normalize, split-pack, write [b*S+s][epair]
    const int b = bh >> 4, h = bh & 15;
    const float inv0 = 1.f / l0r, inv1 = 1.f / l1r;
    const int rA = wid*16 + lr4;
    #pragma unroll
    for (int ni = 0; ni < 8; ni++) {
        const int ep = (h*HDIM + ni*8 + 2*lc4) >> 1;
        uint32_t hw, lw;
        split2(o[ni][0]*inv0, o[ni][1]*inv0, hw, lw);
        size_t w = ((size_t)b*SEQ + q0 + rA) * EW + ep;
        Oh[w] = hw; Ol[w] = lw;
        split2(o[ni][2]*inv1, o[ni][3]*inv1, hw, lw);
        w = ((size_t)b*SEQ + q0 + rA + 8) * EW + ep;
        Oh[w] = hw; Ol[w] = lw;
    }
}

// ============================================================================
// Host launcher — V-GEMM as launch #4 so ncu's capture window hits it.
// ============================================================================
extern "C" void kernel_launch(void* const* d_in, const int* in_sizes, int n_in,
                              void* d_out, int out_size)
{
    (void)in_sizes; (void)n_in; (void)out_size;

    const float* query   = (const float*)d_in[0];
    const float* key     = (const float*)d_in[1];
    const float* value   = (const float*)d_in[2];
    const float* wq      = (const float*)d_in[3];
    const float* bq      = (const float*)d_in[4];
    const float* wk      = (const float*)d_in[5];
    const float* bk      = (const float*)d_in[6];
    const float* wv      = (const float*)d_in[7];
    const float* bv      = (const float*)d_in[8];
    const float* wo      = (const float*)d_in[9];
    const float* bo      = (const float*)d_in[10];
    const float* q_theta = (const float*)d_in[11];
    const float* q_phi   = (const float*)d_in[12];
    const float* q_preW  = (const float*)d_in[13];
    const float* q_preb  = (const float*)d_in[14];
    const float* q_postW = (const float*)d_in[15];
    const float* q_postb = (const float*)d_in[16];
    const float* k_theta = (const float*)d_in[17];
    const float* k_phi   = (const float*)d_in[18];
    const float* k_preW  = (const float*)d_in[19];
    const float* k_preb  = (const float*)d_in[20];
    const float* k_postW = (const float*)d_in[21];
    const float* k_postb = (const float*)d_in[22];
    float* out = (float*)d_out;

    float *pMq, *pMk, *pbq, *pbk, *pVf;
    uint32_t *pWqh, *pWql, *pWkh, *pWkl, *pWvh, *pWvl, *pWoh, *pWol;
    uint32_t *pXqh, *pXql, *pXkh, *pXkl, *pXvh, *pXvl;
    uint32_t *pQh, *pQl, *pKh, *pKl, *pVth, *pVtl, *pOh, *pOl;
    cudaGetSymbolAddress((void**)&pMq, g_Mq);
    cudaGetSymbolAddress((void**)&pMk, g_Mk);
    cudaGetSymbolAddress((void**)&pbq, g_bq);
    cudaGetSymbolAddress((void**)&pbk, g_bk);
    cudaGetSymbolAddress((void**)&pWqh, g_Wqh);
    cudaGetSymbolAddress((void**)&pWql, g_Wql);
    cudaGetSymbolAddress((void**)&pWkh, g_Wkh);
    cudaGetSymbolAddress((void**)&pWkl, g_Wkl);
    cudaGetSymbolAddress((void**)&pWvh, g_Wvh);
    cudaGetSymbolAddress((void**)&pWvl, g_Wvl);
    cudaGetSymbolAddress((void**)&pWoh, g_Woh);
    cudaGetSymbolAddress((void**)&pWol, g_Wol);
    cudaGetSymbolAddress((void**)&pXqh, g_Xqh);
    cudaGetSymbolAddress((void**)&pXql, g_Xql);
    cudaGetSymbolAddress((void**)&pXkh, g_Xkh);
    cudaGetSymbolAddress((void**)&pXkl, g_Xkl);
    cudaGetSymbolAddress((void**)&pXvh, g_Xvh);
    cudaGetSymbolAddress((void**)&pXvl, g_Xvl);
    cudaGetSymbolAddress((void**)&pQh, g_Qh);
    cudaGetSymbolAddress((void**)&pQl, g_Ql);
    cudaGetSymbolAddress((void**)&pKh, g_Kh);
    cudaGetSymbolAddress((void**)&pKl, g_Kl);
    cudaGetSymbolAddress((void**)&pVf, g_Vf);
    cudaGetSymbolAddress((void**)&pVth, g_Vth);
    cudaGetSymbolAddress((void**)&pVtl, g_Vtl);
    cudaGetSymbolAddress((void**)&pOh, g_Oh);
    cudaGetSymbolAddress((void**)&pOl, g_Ol);

    const int gemm_smem = 8 * GB * (int)sizeof(uint32_t);   // 81920
    cudaFuncSetAttribute(bf16_gemm_kernel,
                         cudaFuncAttributeMaxDynamicSharedMemorySize, gemm_smem);
    const int fa_smem = FA_WORDS * (int)sizeof(uint32_t);   // 110592
    cudaFuncSetAttribute(flash_attn_kernel,
                         cudaFuncAttributeMaxDynamicSharedMemorySize, fa_smem);
    dim3 ggrid(E_DIM/128, ROWS/128);

    // Launch 1-3: V-GEMM prerequisites (+ one independent small kernel)
    split_pack_kernel<<<(ROWS*EW)/256, 256>>>(value, pXvh, pXvl, ROWS*EW);
    split_pack_kernel<<<(E_DIM*EW)/256, 256>>>(wv, pWvh, pWvl, E_DIM*EW);
    build_eff_kernel<<<1, 64>>>(q_theta, q_phi, q_preW, q_preb, q_postW, q_postb,
                                bq, pMq, pbq);

    // Launch 4: V projection (ncu capture target)
    bf16_gemm_kernel<<<ggrid, 512, gemm_smem>>>(pXvh, pXvl, pWvh, pWvl, bv,
                                                pVf, nullptr, nullptr, 2);

    // Remaining preprocessing
    build_eff_kernel<<<1, 64>>>(k_theta, k_phi, k_preW, k_preb, k_postW, k_postb,
                                bk, pMk, pbk);
    fold_split_kernel<<<dim3(HEADS, 16), 256>>>(wq, pMq, pWqh, pWql);
    fold_split_kernel<<<dim3(HEADS, 16), 256>>>(wk, pMk, pWkh, pWkl);
    split_pack_kernel<<<(E_DIM*EW)/256, 256>>>(wo, pWoh, pWol, E_DIM*EW);
    split_pack_kernel<<<(ROWS*EW)/256, 256>>>(query, pXqh, pXql, ROWS*EW);
    split_pack_kernel<<<(ROWS*EW)/256, 256>>>(key,   pXkh, pXkl, ROWS*EW);

    // Q/K projections
    bf16_gemm_kernel<<<ggrid, 512, gemm_smem>>>(pXqh, pXql, pWqh, pWql, pbq,
                                                nullptr, pQh, pQl, 1);
    bf16_gemm_kernel<<<ggrid, 512, gemm_smem>>>(pXkh, pXkl, pWkh, pWkl, pbk,
                                                nullptr, pKh, pKl, 1);

    // V transpose+split
    transpose_split_kernel<<<dim3(SEQ/64, BATCH*HEADS), 256>>>(pVf, pVth, pVtl);

    // flash attention
    flash_attn_kernel<<<dim3(SEQ/128, BATCH*HEADS), 256, fa_smem>>>(
        pQh, pQl, pKh, pKl, pVth, pVtl, pOh, pOl);

    // output projection
    bf16_gemm_kernel<<<ggrid, 512, gemm_smem>>>(pOh, pOl, pWoh, pWol, bo,
                                                out, nullptr, nullptr, 0);
}